// round 1
// baseline (speedup 1.0000x reference)
#include <cuda_runtime.h>

#define T_TOK 32768
#define D_DIM 2048
#define NE    8

// ---- Blackwell packed f32x2 helpers ----
__device__ __forceinline__ unsigned long long dup2(float x) {
    unsigned long long r;
    asm("mov.b64 %0, {%1, %1};" : "=l"(r) : "f"(x));
    return r;
}
__device__ __forceinline__ void fma2(unsigned long long& a, unsigned long long b, unsigned long long c) {
    asm("fma.rn.f32x2 %0, %1, %2, %0;" : "+l"(a) : "l"(b), "l"(c));
}
__device__ __forceinline__ unsigned long long add2(unsigned long long a, unsigned long long b) {
    unsigned long long r;
    asm("add.rn.f32x2 %0, %1, %2;" : "=l"(r) : "l"(a), "l"(b));
    return r;
}
__device__ __forceinline__ void unpack2(unsigned long long v, float& lo, float& hi) {
    asm("mov.b64 {%0, %1}, %2;" : "=f"(lo), "=f"(hi) : "l"(v));
}

// Persistent kernel: grid = #SMs, 1 CTA/SM (128KB smem), 512 threads.
// Warp processes 4 tokens; lane = (token_in_group = lane>>3, k_slice = lane&7).
extern "C" __global__ void __launch_bounds__(512, 1)
router_kernel(const float* __restrict__ h,  const float* __restrict__ Ww,
              const float* __restrict__ bw, const float* __restrict__ Wn,
              const float* __restrict__ bn, const float* __restrict__ eps,
              float* __restrict__ out)
{
    extern __shared__ unsigned long long sw[];   // [2048][8] ull == [2048][16] float
    float* swf = (float*)sw;

    const int tid = threadIdx.x;

    // Fill weights into smem, interleaved per-k: [Ww[k][0..7] | Wn[k][0..7]]
    #pragma unroll
    for (int it = 0; it < (D_DIM * NE) / 512; ++it) {
        int idx = tid + it * 512;          // 0..16383
        int k = idx >> 3, e = idx & 7;
        swf[k * 16 + e]     = Ww[idx];
        swf[k * 16 + 8 + e] = Wn[idx];
    }
    __syncthreads();

    const int bid = blockIdx.x;
    const int t0 = (int)(((long long)T_TOK * bid)       / gridDim.x);
    const int t1 = (int)(((long long)T_TOK * (bid + 1)) / gridDim.x);

    const int warp = tid >> 5;
    const int lane = tid & 31;
    const int sub  = lane & 7;     // k-slice within token
    const int trow = lane >> 3;    // token within warp group

    for (int gbase = t0 + warp * 4; gbase < t1; gbase += 16 * 4) {
        const int tok  = gbase + trow;
        const int tokc = (tok < t1) ? tok : (t1 - 1);     // clamp (dup compute, store guarded)

        const float4* hp = ((const float4*)h) + (size_t)tokc * (D_DIM / 4) + sub;

        unsigned long long acc[8];
        #pragma unroll
        for (int i = 0; i < 8; ++i) acc[i] = 0ull;

        float4 hv = __ldg(hp);
        #pragma unroll 4
        for (int i = 0; i < D_DIM / 32; ++i) {            // 64 iters, 32 k per iter
            float4 cur = hv;
            if (i < D_DIM / 32 - 1) hv = __ldg(hp + (i + 1) * 8);

            const int kbase = i * 32 + sub * 4;
            const unsigned long long* row = sw + (size_t)kbase * 8;
            float c4[4] = {cur.x, cur.y, cur.z, cur.w};

            #pragma unroll
            for (int j = 0; j < 4; ++j) {
                unsigned long long hh = dup2(c4[j]);
                const ulonglong2* r2 = (const ulonglong2*)(row + j * 8);
                ulonglong2 w01 = r2[0];
                ulonglong2 w23 = r2[1];
                ulonglong2 n01 = r2[2];
                ulonglong2 n23 = r2[3];
                fma2(acc[0], w01.x, hh); fma2(acc[1], w01.y, hh);
                fma2(acc[2], w23.x, hh); fma2(acc[3], w23.y, hh);
                fma2(acc[4], n01.x, hh); fma2(acc[5], n01.y, hh);
                fma2(acc[6], n23.x, hh); fma2(acc[7], n23.y, hh);
            }
        }

        // Reduce across the 8 k-slice lanes of each token
        #pragma unroll
        for (int s = 4; s >= 1; s >>= 1) {
            #pragma unroll
            for (int i = 0; i < 8; ++i) {
                unsigned long long o = __shfl_xor_sync(0xffffffffu, acc[i], s);
                acc[i] = add2(acc[i], o);
            }
        }

        if (sub == 0 && tok < t1) {
            float lg[8], nr[8];
            unpack2(acc[0], lg[0], lg[1]); unpack2(acc[1], lg[2], lg[3]);
            unpack2(acc[2], lg[4], lg[5]); unpack2(acc[3], lg[6], lg[7]);
            unpack2(acc[4], nr[0], nr[1]); unpack2(acc[5], nr[2], nr[3]);
            unpack2(acc[6], nr[4], nr[5]); unpack2(acc[7], nr[6], nr[7]);

            float4 e0 = __ldg((const float4*)(eps + (size_t)tok * 8));
            float4 e1 = __ldg((const float4*)(eps + (size_t)tok * 8) + 1);
            float ee[8] = {e0.x, e0.y, e0.z, e0.w, e1.x, e1.y, e1.z, e1.w};

            float noisy[8];
            #pragma unroll
            for (int e = 0; e < 8; ++e) {
                float x  = nr[e] + bn[e];
                float sp = (x > 0.f) ? (x + log1pf(expf(-x))) : log1pf(expf(x));
                noisy[e] = lg[e] + bw[e] + ee[e] * sp;
            }

            // Full softmax (max-subtracted, matches jax.nn.softmax)
            float m = noisy[0];
            #pragma unroll
            for (int e = 1; e < 8; ++e) m = fmaxf(m, noisy[e]);
            float ex[8], ssum = 0.f;
            #pragma unroll
            for (int e = 0; e < 8; ++e) { ex[e] = expf(noisy[e] - m); ssum += ex[e]; }
            float inv = 1.f / ssum;

            // Top-2, first-occurrence tie-break (matches jax.lax.top_k)
            int i1 = 0; float v1 = noisy[0];
            #pragma unroll
            for (int e = 1; e < 8; ++e) if (noisy[e] > v1) { v1 = noisy[e]; i1 = e; }
            int i2 = -1; float v2 = -3.4e38f;
            #pragma unroll
            for (int e = 0; e < 8; ++e) if (e != i1 && noisy[e] > v2) { v2 = noisy[e]; i2 = e; }

            // Sparse softmax over exactly the two kept entries (others exactly 0)
            float edd = expf(v2 - v1);
            float s1  = 1.f / (1.f + edd);
            float s2  = edd * s1;

            float sp8[8];
            #pragma unroll
            for (int e = 0; e < 8; ++e)
                sp8[e] = (e == i1) ? s1 : ((e == i2) ? s2 : 0.f);

            float* outS = out + (size_t)tok * 8;
            float* outI = out + (size_t)T_TOK * 8  + (size_t)tok * 2;
            float* outF = out + (size_t)T_TOK * 10 + (size_t)tok * 8;

            ((float4*)outS)[0] = make_float4(sp8[0], sp8[1], sp8[2], sp8[3]);
            ((float4*)outS)[1] = make_float4(sp8[4], sp8[5], sp8[6], sp8[7]);
            ((float2*)outI)[0] = make_float2((float)i1, (float)i2);
            ((float4*)outF)[0] = make_float4(ex[0] * inv, ex[1] * inv, ex[2] * inv, ex[3] * inv);
            ((float4*)outF)[1] = make_float4(ex[4] * inv, ex[5] * inv, ex[6] * inv, ex[7] * inv);
        }
    }
}

extern "C" void kernel_launch(void* const* d_in, const int* in_sizes, int n_in,
                              void* d_out, int out_size)
{
    const float* h   = (const float*)d_in[0];
    const float* Ww  = (const float*)d_in[1];
    const float* bw  = (const float*)d_in[2];
    const float* Wn  = (const float*)d_in[3];
    const float* bn  = (const float*)d_in[4];
    const float* eps = (const float*)d_in[5];

    const int smem = D_DIM * 16 * sizeof(float);   // 131072 bytes
    cudaFuncSetAttribute(router_kernel, cudaFuncAttributeMaxDynamicSharedMemorySize, smem);

    int nsm = 148;
    cudaDeviceGetAttribute(&nsm, cudaDevAttrMultiProcessorCount, 0);

    router_kernel<<<nsm, 512, smem>>>(h, Ww, bw, Wn, bn, eps, (float*)d_out);
}

// round 2
// speedup vs baseline: 5.9544x; 5.9544x over previous
#include <cuda_runtime.h>

#define T_TOK 32768
#define D_DIM 2048
#define NE    8

// ---- Blackwell packed f32x2 helpers ----
__device__ __forceinline__ unsigned long long dup2(float x) {
    unsigned long long r;
    asm("mov.b64 %0, {%1, %1};" : "=l"(r) : "f"(x));
    return r;
}
__device__ __forceinline__ void fma2(unsigned long long& a, unsigned long long b, unsigned long long c) {
    asm("fma.rn.f32x2 %0, %1, %2, %0;" : "+l"(a) : "l"(b), "l"(c));
}
__device__ __forceinline__ unsigned long long add2(unsigned long long a, unsigned long long b) {
    unsigned long long r;
    asm("add.rn.f32x2 %0, %1, %2;" : "=l"(r) : "l"(a), "l"(b));
    return r;
}
__device__ __forceinline__ void unpack2(unsigned long long v, float& lo, float& hi) {
    asm("mov.b64 {%0, %1}, %2;" : "=f"(lo), "=f"(hi) : "l"(v));
}

// Persistent kernel: grid = #SMs, 1 CTA/SM (128KB smem), 512 threads.
// Warp processes 4 tokens; lane = (token_in_group = lane>>3, k_slice = lane&7).
// Weight smem layout is XOR-swizzled: byte addr ^= (((k>>2)&7) << 4) so the 8
// k-slice lanes land on 8 distinct 16B bank-slots (conflict-free LDS.128 with
// 4-lane broadcast).
extern "C" __global__ void __launch_bounds__(512, 1)
router_kernel(const float* __restrict__ h,  const float* __restrict__ Ww,
              const float* __restrict__ bw, const float* __restrict__ Wn,
              const float* __restrict__ bn, const float* __restrict__ eps,
              float* __restrict__ out)
{
    extern __shared__ unsigned long long sw[];   // 2048 rows x 64B, swizzled
    char* swb = (char*)sw;

    const int tid = threadIdx.x;

    // Fill weights into smem with swizzle.
    // Logical per-k row (64B): [Ww e0..7 | Wn e0..7]; swizzle XORs ((k>>2)&7)<<4.
    #pragma unroll
    for (int it = 0; it < (D_DIM * NE) / 512; ++it) {
        int idx = tid + it * 512;          // 0..16383
        int k = idx >> 3, e = idx & 7;
        unsigned sx = ((unsigned)(k >> 2) & 7u) << 4;
        unsigned offW = ((unsigned)k * 64u + (unsigned)e * 4u) ^ sx;
        unsigned offN = ((unsigned)k * 64u + 32u + (unsigned)e * 4u) ^ sx;
        *(float*)(swb + offW) = Ww[idx];
        *(float*)(swb + offN) = Wn[idx];
    }
    __syncthreads();

    const int bid = blockIdx.x;
    const int t0 = (int)(((long long)T_TOK * bid)       / gridDim.x);
    const int t1 = (int)(((long long)T_TOK * (bid + 1)) / gridDim.x);

    const int warp = tid >> 5;
    const int lane = tid & 31;
    const int sub  = lane & 7;     // k-slice within token
    const int trow = lane >> 3;    // token within warp group
    const unsigned subx = (unsigned)sub << 4;

    for (int gbase = t0 + warp * 4; gbase < t1; gbase += 16 * 4) {
        const int tok  = gbase + trow;
        const int tokc = (tok < t1) ? tok : (t1 - 1);     // clamp (dup compute, store guarded)

        const float4* hp = ((const float4*)h) + (size_t)tokc * (D_DIM / 4) + sub;

        unsigned long long acc[8];
        #pragma unroll
        for (int i = 0; i < 8; ++i) acc[i] = 0ull;

        float4 hv0 = __ldg(hp);
        float4 hv1 = __ldg(hp + 8);
        #pragma unroll 4
        for (int i = 0; i < D_DIM / 32; ++i) {            // 64 iters, 32 k per iter
            float4 cur = hv0;
            hv0 = hv1;
            if (i < D_DIM / 32 - 2) hv1 = __ldg(hp + (i + 2) * 8);

            const int kbase = i * 32 + sub * 4;
            float c4[4] = {cur.x, cur.y, cur.z, cur.w};

            #pragma unroll
            for (int j = 0; j < 4; ++j) {
                const int k = kbase + j;
                const unsigned base = ((unsigned)k * 64u) ^ subx;   // swizzled row base
                unsigned long long hh = dup2(c4[j]);
                ulonglong2 w01 = *(const ulonglong2*)(swb + (base ^ 0u));
                ulonglong2 w23 = *(const ulonglong2*)(swb + (base ^ 16u));
                ulonglong2 n01 = *(const ulonglong2*)(swb + (base ^ 32u));
                ulonglong2 n23 = *(const ulonglong2*)(swb + (base ^ 48u));
                fma2(acc[0], w01.x, hh); fma2(acc[1], w01.y, hh);
                fma2(acc[2], w23.x, hh); fma2(acc[3], w23.y, hh);
                fma2(acc[4], n01.x, hh); fma2(acc[5], n01.y, hh);
                fma2(acc[6], n23.x, hh); fma2(acc[7], n23.y, hh);
            }
        }

        // Reduce across the 8 k-slice lanes of each token
        #pragma unroll
        for (int s = 4; s >= 1; s >>= 1) {
            #pragma unroll
            for (int i = 0; i < 8; ++i) {
                unsigned long long o = __shfl_xor_sync(0xffffffffu, acc[i], s);
                acc[i] = add2(acc[i], o);
            }
        }

        if (sub == 0 && tok < t1) {
            float lg[8], nr[8];
            unpack2(acc[0], lg[0], lg[1]); unpack2(acc[1], lg[2], lg[3]);
            unpack2(acc[2], lg[4], lg[5]); unpack2(acc[3], lg[6], lg[7]);
            unpack2(acc[4], nr[0], nr[1]); unpack2(acc[5], nr[2], nr[3]);
            unpack2(acc[6], nr[4], nr[5]); unpack2(acc[7], nr[6], nr[7]);

            float4 e0 = __ldg((const float4*)(eps + (size_t)tok * 8));
            float4 e1 = __ldg((const float4*)(eps + (size_t)tok * 8) + 1);
            float ee[8] = {e0.x, e0.y, e0.z, e0.w, e1.x, e1.y, e1.z, e1.w};

            float noisy[8];
            #pragma unroll
            for (int e = 0; e < 8; ++e) {
                float x  = nr[e] + bn[e];
                float sp = (x > 0.f) ? (x + log1pf(expf(-x))) : log1pf(expf(x));
                noisy[e] = lg[e] + bw[e] + ee[e] * sp;
            }

            // Full softmax (max-subtracted, matches jax.nn.softmax)
            float m = noisy[0];
            #pragma unroll
            for (int e = 1; e < 8; ++e) m = fmaxf(m, noisy[e]);
            float ex[8], ssum = 0.f;
            #pragma unroll
            for (int e = 0; e < 8; ++e) { ex[e] = expf(noisy[e] - m); ssum += ex[e]; }
            float inv = 1.f / ssum;

            // Top-2, first-occurrence tie-break (matches jax.lax.top_k)
            int i1 = 0; float v1 = noisy[0];
            #pragma unroll
            for (int e = 1; e < 8; ++e) if (noisy[e] > v1) { v1 = noisy[e]; i1 = e; }
            int i2 = -1; float v2 = -3.4e38f;
            #pragma unroll
            for (int e = 0; e < 8; ++e) if (e != i1 && noisy[e] > v2) { v2 = noisy[e]; i2 = e; }

            // Sparse softmax over exactly the two kept entries (others exactly 0)
            float edd = expf(v2 - v1);
            float s1  = 1.f / (1.f + edd);
            float s2  = edd * s1;

            float sp8[8];
            #pragma unroll
            for (int e = 0; e < 8; ++e)
                sp8[e] = (e == i1) ? s1 : ((e == i2) ? s2 : 0.f);

            float* outS = out + (size_t)tok * 8;
            float* outI = out + (size_t)T_TOK * 8  + (size_t)tok * 2;
            float* outF = out + (size_t)T_TOK * 10 + (size_t)tok * 8;

            ((float4*)outS)[0] = make_float4(sp8[0], sp8[1], sp8[2], sp8[3]);
            ((float4*)outS)[1] = make_float4(sp8[4], sp8[5], sp8[6], sp8[7]);
            ((float2*)outI)[0] = make_float2((float)i1, (float)i2);
            ((float4*)outF)[0] = make_float4(ex[0] * inv, ex[1] * inv, ex[2] * inv, ex[3] * inv);
            ((float4*)outF)[1] = make_float4(ex[4] * inv, ex[5] * inv, ex[6] * inv, ex[7] * inv);
        }
    }
}

extern "C" void kernel_launch(void* const* d_in, const int* in_sizes, int n_in,
                              void* d_out, int out_size)
{
    const float* h   = (const float*)d_in[0];
    const float* Ww  = (const float*)d_in[1];
    const float* bw  = (const float*)d_in[2];
    const float* Wn  = (const float*)d_in[3];
    const float* bn  = (const float*)d_in[4];
    const float* eps = (const float*)d_in[5];

    const int smem = D_DIM * 16 * sizeof(float);   // 131072 bytes
    cudaFuncSetAttribute(router_kernel, cudaFuncAttributeMaxDynamicSharedMemorySize, smem);

    int nsm = 148;
    cudaDeviceGetAttribute(&nsm, cudaDevAttrMultiProcessorCount, 0);

    router_kernel<<<nsm, 512, smem>>>(h, Ww, bw, Wn, bn, eps, (float*)d_out);
}

// round 3
// speedup vs baseline: 10.6552x; 1.7895x over previous
#include <cuda_runtime.h>

#define T_TOK   32768
#define D_DIM   2048
#define NE      8
#define NGROUPS (T_TOK / 16)   // 2048 groups of 16 tokens, exact

// ---- Blackwell packed f32x2 helpers ----
__device__ __forceinline__ unsigned long long dup2(float x) {
    unsigned long long r;
    asm("mov.b64 %0, {%1, %1};" : "=l"(r) : "f"(x));
    return r;
}
__device__ __forceinline__ void fma2(unsigned long long& a, unsigned long long b, unsigned long long c) {
    asm("fma.rn.f32x2 %0, %1, %2, %0;" : "+l"(a) : "l"(b), "l"(c));
}
__device__ __forceinline__ unsigned long long add2(unsigned long long a, unsigned long long b) {
    unsigned long long r;
    asm("add.rn.f32x2 %0, %1, %2;" : "=l"(r) : "l"(a), "l"(b));
    return r;
}
__device__ __forceinline__ void unpack2(unsigned long long v, float& lo, float& hi) {
    asm("mov.b64 {%0, %1}, %2;" : "=f"(lo), "=f"(hi) : "l"(v));
}

// Persistent kernel: grid = #SMs, 1 CTA/SM, 256 threads, 128KB smem of
// XOR-swizzled weights ([k][Ww e0..7 | Wn e0..7], addr ^= ((k>>2)&7)<<4).
// Lane = (sub = lane>>2: k-slice 0..7, trow = lane&3: token quad 0..3).
// Each lane accumulates T=4 tokens -> one 64B weight LDS feeds 32 FMA2.
extern "C" __global__ void __launch_bounds__(256, 1)
router_kernel(const float* __restrict__ h,  const float* __restrict__ Ww,
              const float* __restrict__ bw, const float* __restrict__ Wn,
              const float* __restrict__ bn, const float* __restrict__ eps,
              float* __restrict__ out)
{
    extern __shared__ unsigned long long sw[];   // 2048 rows x 64B, swizzled
    char* swb = (char*)sw;

    const int tid = threadIdx.x;

    // Fill weights into smem with swizzle.
    #pragma unroll
    for (int it = 0; it < (D_DIM * NE) / 256; ++it) {
        int idx = tid + it * 256;          // 0..16383
        int k = idx >> 3, e = idx & 7;
        unsigned sx = ((unsigned)(k >> 2) & 7u) << 4;
        unsigned offW = ((unsigned)k * 64u + (unsigned)e * 4u) ^ sx;
        unsigned offN = ((unsigned)k * 64u + 32u + (unsigned)e * 4u) ^ sx;
        *(float*)(swb + offW) = Ww[idx];
        *(float*)(swb + offN) = Wn[idx];
    }
    __syncthreads();

    const int warp = tid >> 5;
    const int lane = tid & 31;
    const int trow = lane & 3;           // token quad within warp
    const int sub  = lane >> 2;          // k-slice 0..7
    const unsigned subx = (unsigned)sub << 4;   // swizzle term ((k>>2)&7)==sub

    const int gwarp  = blockIdx.x * 8 + warp;
    const int nwarps = gridDim.x * 8;

    for (int g = gwarp; g < NGROUPS; g += nwarps) {
        const int tokb = g * 16 + trow * 4;     // this lane's 4 tokens: tokb..tokb+3

        const float4* hp0 = (const float4*)h + (size_t)(tokb + 0) * (D_DIM / 4) + sub;
        const float4* hp1 = (const float4*)h + (size_t)(tokb + 1) * (D_DIM / 4) + sub;
        const float4* hp2 = (const float4*)h + (size_t)(tokb + 2) * (D_DIM / 4) + sub;
        const float4* hp3 = (const float4*)h + (size_t)(tokb + 3) * (D_DIM / 4) + sub;

        unsigned long long acc[4][8];
        #pragma unroll
        for (int r = 0; r < 4; ++r)
            #pragma unroll
            for (int e = 0; e < 8; ++e) acc[r][e] = 0ull;

        // distance-2 prefetch, 4 token streams
        float4 n1_0 = __ldg(hp0),     n1_1 = __ldg(hp1),     n1_2 = __ldg(hp2),     n1_3 = __ldg(hp3);
        float4 n2_0 = __ldg(hp0 + 8), n2_1 = __ldg(hp1 + 8), n2_2 = __ldg(hp2 + 8), n2_3 = __ldg(hp3 + 8);

        #pragma unroll 2
        for (int i = 0; i < D_DIM / 32; ++i) {          // 64 iters, 32 k each
            float4 c0 = n1_0, c1 = n1_1, c2 = n1_2, c3 = n1_3;
            n1_0 = n2_0; n1_1 = n2_1; n1_2 = n2_2; n1_3 = n2_3;
            int ip = (i + 2 < D_DIM / 32) ? (i + 2) : (D_DIM / 32 - 1);
            n2_0 = __ldg(hp0 + ip * 8);
            n2_1 = __ldg(hp1 + ip * 8);
            n2_2 = __ldg(hp2 + ip * 8);
            n2_3 = __ldg(hp3 + ip * 8);

            const float cc[4][4] = {
                {c0.x, c0.y, c0.z, c0.w},
                {c1.x, c1.y, c1.z, c1.w},
                {c2.x, c2.y, c2.z, c2.w},
                {c3.x, c3.y, c3.z, c3.w}
            };

            const int kbase = i * 32 + sub * 4;
            #pragma unroll
            for (int j = 0; j < 4; ++j) {
                const unsigned base = ((unsigned)(kbase + j) * 64u) ^ subx;
                ulonglong2 w01 = *(const ulonglong2*)(swb + (base ^ 0u));
                ulonglong2 w23 = *(const ulonglong2*)(swb + (base ^ 16u));
                ulonglong2 n01 = *(const ulonglong2*)(swb + (base ^ 32u));
                ulonglong2 n23 = *(const ulonglong2*)(swb + (base ^ 48u));
                #pragma unroll
                for (int r = 0; r < 4; ++r) {
                    unsigned long long hh = dup2(cc[r][j]);
                    fma2(acc[r][0], w01.x, hh); fma2(acc[r][1], w01.y, hh);
                    fma2(acc[r][2], w23.x, hh); fma2(acc[r][3], w23.y, hh);
                    fma2(acc[r][4], n01.x, hh); fma2(acc[r][5], n01.y, hh);
                    fma2(acc[r][6], n23.x, hh); fma2(acc[r][7], n23.y, hh);
                }
            }
        }

        // Butterfly-reduce across the 8 sub lanes (xor 4, 8, 16).
        // Afterwards every lane holds full sums for its trow's 4 tokens.
        #pragma unroll
        for (int s = 4; s <= 16; s <<= 1) {
            #pragma unroll
            for (int r = 0; r < 4; ++r)
                #pragma unroll
                for (int e = 0; e < 8; ++e) {
                    unsigned long long o = __shfl_xor_sync(0xffffffffu, acc[r][e], s);
                    acc[r][e] = add2(acc[r][e], o);
                }
        }

        // Lanes with sub<4 each finish one token: r = sub.
        if (sub < 4) {
            unsigned long long sel[8];
            #pragma unroll
            for (int r = 0; r < 4; ++r)
                if (sub == r) {
                    #pragma unroll
                    for (int e = 0; e < 8; ++e) sel[e] = acc[r][e];
                }

            const int tok = tokb + sub;

            float lg[8], nr[8];
            unpack2(sel[0], lg[0], lg[1]); unpack2(sel[1], lg[2], lg[3]);
            unpack2(sel[2], lg[4], lg[5]); unpack2(sel[3], lg[6], lg[7]);
            unpack2(sel[4], nr[0], nr[1]); unpack2(sel[5], nr[2], nr[3]);
            unpack2(sel[6], nr[4], nr[5]); unpack2(sel[7], nr[6], nr[7]);

            float4 e0 = __ldg((const float4*)(eps + (size_t)tok * 8));
            float4 e1 = __ldg((const float4*)(eps + (size_t)tok * 8) + 1);
            float ee[8] = {e0.x, e0.y, e0.z, e0.w, e1.x, e1.y, e1.z, e1.w};

            float noisy[8];
            #pragma unroll
            for (int e = 0; e < 8; ++e) {
                float x  = nr[e] + bn[e];
                float sp = (x > 0.f) ? (x + log1pf(expf(-x))) : log1pf(expf(x));
                noisy[e] = lg[e] + bw[e] + ee[e] * sp;
            }

            // Full softmax (max-subtracted, matches jax.nn.softmax)
            float m = noisy[0];
            #pragma unroll
            for (int e = 1; e < 8; ++e) m = fmaxf(m, noisy[e]);
            float ex[8], ssum = 0.f;
            #pragma unroll
            for (int e = 0; e < 8; ++e) { ex[e] = expf(noisy[e] - m); ssum += ex[e]; }
            float inv = 1.f / ssum;

            // Top-2, first-occurrence tie-break (matches jax.lax.top_k)
            int i1 = 0; float v1 = noisy[0];
            #pragma unroll
            for (int e = 1; e < 8; ++e) if (noisy[e] > v1) { v1 = noisy[e]; i1 = e; }
            int i2 = -1; float v2 = -3.4e38f;
            #pragma unroll
            for (int e = 0; e < 8; ++e) if (e != i1 && noisy[e] > v2) { v2 = noisy[e]; i2 = e; }

            // Sparse softmax over exactly the two kept entries (others exactly 0)
            float edd = expf(v2 - v1);
            float s1  = 1.f / (1.f + edd);
            float s2  = edd * s1;

            float sp8[8];
            #pragma unroll
            for (int e = 0; e < 8; ++e)
                sp8[e] = (e == i1) ? s1 : ((e == i2) ? s2 : 0.f);

            float* outS = out + (size_t)tok * 8;
            float* outI = out + (size_t)T_TOK * 8  + (size_t)tok * 2;
            float* outF = out + (size_t)T_TOK * 10 + (size_t)tok * 8;

            ((float4*)outS)[0] = make_float4(sp8[0], sp8[1], sp8[2], sp8[3]);
            ((float4*)outS)[1] = make_float4(sp8[4], sp8[5], sp8[6], sp8[7]);
            ((float2*)outI)[0] = make_float2((float)i1, (float)i2);
            ((float4*)outF)[0] = make_float4(ex[0] * inv, ex[1] * inv, ex[2] * inv, ex[3] * inv);
            ((float4*)outF)[1] = make_float4(ex[4] * inv, ex[5] * inv, ex[6] * inv, ex[7] * inv);
        }
    }
}

extern "C" void kernel_launch(void* const* d_in, const int* in_sizes, int n_in,
                              void* d_out, int out_size)
{
    const float* h   = (const float*)d_in[0];
    const float* Ww  = (const float*)d_in[1];
    const float* bw  = (const float*)d_in[2];
    const float* Wn  = (const float*)d_in[3];
    const float* bn  = (const float*)d_in[4];
    const float* eps = (const float*)d_in[5];

    const int smem = D_DIM * 16 * sizeof(float);   // 131072 bytes
    cudaFuncSetAttribute(router_kernel, cudaFuncAttributeMaxDynamicSharedMemorySize, smem);

    int nsm = 148;
    cudaDeviceGetAttribute(&nsm, cudaDevAttrMultiProcessorCount, 0);

    router_kernel<<<nsm, 256, smem>>>(h, Ww, bw, Wn, bn, eps, (float*)d_out);
}

// round 4
// speedup vs baseline: 12.7882x; 1.2002x over previous
#include <cuda_runtime.h>

#define T_TOK   32768
#define D_DIM   2048
#define NE      8
#define NGROUPS (T_TOK / 32)   // 1024 groups of 32 tokens, exact

// ---- Blackwell packed f32x2 helpers ----
__device__ __forceinline__ unsigned long long dup2(float x) {
    unsigned long long r;
    asm("mov.b64 %0, {%1, %1};" : "=l"(r) : "f"(x));
    return r;
}
__device__ __forceinline__ void fma2(unsigned long long& a, unsigned long long b, unsigned long long c) {
    asm("fma.rn.f32x2 %0, %1, %2, %0;" : "+l"(a) : "l"(b), "l"(c));
}
__device__ __forceinline__ unsigned long long add2(unsigned long long a, unsigned long long b) {
    unsigned long long r;
    asm("add.rn.f32x2 %0, %1, %2;" : "=l"(r) : "l"(a), "l"(b));
    return r;
}
__device__ __forceinline__ void unpack2(unsigned long long v, float& lo, float& hi) {
    asm("mov.b64 {%0, %1}, %2;" : "=f"(lo), "=f"(hi) : "l"(v));
}

// Persistent kernel: grid = #SMs, 1 CTA/SM, 256 threads, 128KB smem of
// XOR-swizzled weights ([k][Ww e0..7 | Wn e0..7], addr ^= ((k>>2)&7)<<4).
// Lane = (sub = lane>>2: k-slice 0..7, trow = lane&3: token octet 0..3).
// Each lane accumulates T=8 tokens -> one 64B weight LDS feeds 64 FMA2.
extern "C" __global__ void __launch_bounds__(256, 1)
router_kernel(const float* __restrict__ h,  const float* __restrict__ Ww,
              const float* __restrict__ bw, const float* __restrict__ Wn,
              const float* __restrict__ bn, const float* __restrict__ eps,
              float* __restrict__ out)
{
    extern __shared__ unsigned long long sw[];   // 2048 rows x 64B, swizzled
    char* swb = (char*)sw;

    const int tid = threadIdx.x;

    // Fill weights into smem with swizzle.
    #pragma unroll
    for (int it = 0; it < (D_DIM * NE) / 256; ++it) {
        int idx = tid + it * 256;          // 0..16383
        int k = idx >> 3, e = idx & 7;
        unsigned sx = ((unsigned)(k >> 2) & 7u) << 4;
        unsigned offW = ((unsigned)k * 64u + (unsigned)e * 4u) ^ sx;
        unsigned offN = ((unsigned)k * 64u + 32u + (unsigned)e * 4u) ^ sx;
        *(float*)(swb + offW) = Ww[idx];
        *(float*)(swb + offN) = Wn[idx];
    }
    __syncthreads();

    const int warp = tid >> 5;
    const int lane = tid & 31;
    const int trow = lane & 3;           // token octet within warp
    const int sub  = lane >> 2;          // k-slice 0..7
    const unsigned subx = (unsigned)sub << 4;   // swizzle term

    const int nwarps = gridDim.x * 8;
    // Spread active warps evenly across SMs: same warp-id on every SM first.
    for (int g = warp * gridDim.x + blockIdx.x; g < NGROUPS; g += nwarps) {
        const int tokb = g * 32 + trow * 8;     // this lane's 8 tokens

        // one base pointer; token r is at +r*512 float4s (const offsets in SASS)
        const float4* hp = (const float4*)h + (size_t)tokb * (D_DIM / 4) + sub;

        unsigned long long acc[8][8];
        #pragma unroll
        for (int r = 0; r < 8; ++r)
            #pragma unroll
            for (int e = 0; e < 8; ++e) acc[r][e] = 0ull;

        // distance-1 prefetch across 8 token streams
        float4 buf[8];
        #pragma unroll
        for (int r = 0; r < 8; ++r) buf[r] = __ldg(hp + r * 512);

        #pragma unroll 2
        for (int i = 0; i < D_DIM / 32; ++i) {          // 64 iters, 32 k each
            float4 nb[8];
            const int ip = (i + 1 < D_DIM / 32) ? (i + 1) : (D_DIM / 32 - 1);
            #pragma unroll
            for (int r = 0; r < 8; ++r) nb[r] = __ldg(hp + r * 512 + ip * 8);

            const float cc[8][4] = {
                {buf[0].x, buf[0].y, buf[0].z, buf[0].w},
                {buf[1].x, buf[1].y, buf[1].z, buf[1].w},
                {buf[2].x, buf[2].y, buf[2].z, buf[2].w},
                {buf[3].x, buf[3].y, buf[3].z, buf[3].w},
                {buf[4].x, buf[4].y, buf[4].z, buf[4].w},
                {buf[5].x, buf[5].y, buf[5].z, buf[5].w},
                {buf[6].x, buf[6].y, buf[6].z, buf[6].w},
                {buf[7].x, buf[7].y, buf[7].z, buf[7].w}
            };

            const int kbase = i * 32 + sub * 4;
            #pragma unroll
            for (int j = 0; j < 4; ++j) {
                const unsigned base = ((unsigned)(kbase + j) * 64u) ^ subx;
                ulonglong2 w01 = *(const ulonglong2*)(swb + (base ^ 0u));
                ulonglong2 w23 = *(const ulonglong2*)(swb + (base ^ 16u));
                ulonglong2 n01 = *(const ulonglong2*)(swb + (base ^ 32u));
                ulonglong2 n23 = *(const ulonglong2*)(swb + (base ^ 48u));
                #pragma unroll
                for (int r = 0; r < 8; ++r) {
                    unsigned long long hh = dup2(cc[r][j]);
                    fma2(acc[r][0], w01.x, hh); fma2(acc[r][1], w01.y, hh);
                    fma2(acc[r][2], w23.x, hh); fma2(acc[r][3], w23.y, hh);
                    fma2(acc[r][4], n01.x, hh); fma2(acc[r][5], n01.y, hh);
                    fma2(acc[r][6], n23.x, hh); fma2(acc[r][7], n23.y, hh);
                }
            }

            #pragma unroll
            for (int r = 0; r < 8; ++r) buf[r] = nb[r];
        }

        // Butterfly-reduce across the 8 sub lanes (xor 4, 8, 16).
        // Afterwards every lane holds full sums for its trow's 8 tokens.
        #pragma unroll
        for (int s = 4; s <= 16; s <<= 1) {
            #pragma unroll
            for (int r = 0; r < 8; ++r)
                #pragma unroll
                for (int e = 0; e < 8; ++e) {
                    unsigned long long o = __shfl_xor_sync(0xffffffffu, acc[r][e], s);
                    acc[r][e] = add2(acc[r][e], o);
                }
        }

        // Every lane finishes exactly one token: r = sub (0..7).
        {
            unsigned long long sel[8];
            #pragma unroll
            for (int r = 0; r < 8; ++r)
                if (sub == r) {
                    #pragma unroll
                    for (int e = 0; e < 8; ++e) sel[e] = acc[r][e];
                }

            const int tok = tokb + sub;

            float lg[8], nr[8];
            unpack2(sel[0], lg[0], lg[1]); unpack2(sel[1], lg[2], lg[3]);
            unpack2(sel[2], lg[4], lg[5]); unpack2(sel[3], lg[6], lg[7]);
            unpack2(sel[4], nr[0], nr[1]); unpack2(sel[5], nr[2], nr[3]);
            unpack2(sel[6], nr[4], nr[5]); unpack2(sel[7], nr[6], nr[7]);

            float4 e0 = __ldg((const float4*)(eps + (size_t)tok * 8));
            float4 e1 = __ldg((const float4*)(eps + (size_t)tok * 8) + 1);
            float ee[8] = {e0.x, e0.y, e0.z, e0.w, e1.x, e1.y, e1.z, e1.w};

            float noisy[8];
            #pragma unroll
            for (int e = 0; e < 8; ++e) {
                float x  = nr[e] + bn[e];
                float sp = (x > 0.f) ? (x + log1pf(expf(-x))) : log1pf(expf(x));
                noisy[e] = lg[e] + bw[e] + ee[e] * sp;
            }

            // Full softmax (max-subtracted, matches jax.nn.softmax)
            float m = noisy[0];
            #pragma unroll
            for (int e = 1; e < 8; ++e) m = fmaxf(m, noisy[e]);
            float ex[8], ssum = 0.f;
            #pragma unroll
            for (int e = 0; e < 8; ++e) { ex[e] = expf(noisy[e] - m); ssum += ex[e]; }
            float inv = 1.f / ssum;

            // Top-2, first-occurrence tie-break (matches jax.lax.top_k)
            int i1 = 0; float v1 = noisy[0];
            #pragma unroll
            for (int e = 1; e < 8; ++e) if (noisy[e] > v1) { v1 = noisy[e]; i1 = e; }
            int i2 = -1; float v2 = -3.4e38f;
            #pragma unroll
            for (int e = 0; e < 8; ++e) if (e != i1 && noisy[e] > v2) { v2 = noisy[e]; i2 = e; }

            // Sparse softmax over exactly the two kept entries (others exactly 0)
            float edd = expf(v2 - v1);
            float s1  = 1.f / (1.f + edd);
            float s2  = edd * s1;

            float sp8[8];
            #pragma unroll
            for (int e = 0; e < 8; ++e)
                sp8[e] = (e == i1) ? s1 : ((e == i2) ? s2 : 0.f);

            float* outS = out + (size_t)tok * 8;
            float* outI = out + (size_t)T_TOK * 8  + (size_t)tok * 2;
            float* outF = out + (size_t)T_TOK * 10 + (size_t)tok * 8;

            ((float4*)outS)[0] = make_float4(sp8[0], sp8[1], sp8[2], sp8[3]);
            ((float4*)outS)[1] = make_float4(sp8[4], sp8[5], sp8[6], sp8[7]);
            ((float2*)outI)[0] = make_float2((float)i1, (float)i2);
            ((float4*)outF)[0] = make_float4(ex[0] * inv, ex[1] * inv, ex[2] * inv, ex[3] * inv);
            ((float4*)outF)[1] = make_float4(ex[4] * inv, ex[5] * inv, ex[6] * inv, ex[7] * inv);
        }
    }
}

extern "C" void kernel_launch(void* const* d_in, const int* in_sizes, int n_in,
                              void* d_out, int out_size)
{
    const float* h   = (const float*)d_in[0];
    const float* Ww  = (const float*)d_in[1];
    const float* bw  = (const float*)d_in[2];
    const float* Wn  = (const float*)d_in[3];
    const float* bn  = (const float*)d_in[4];
    const float* eps = (const float*)d_in[5];

    const int smem = D_DIM * 16 * sizeof(float);   // 131072 bytes
    cudaFuncSetAttribute(router_kernel, cudaFuncAttributeMaxDynamicSharedMemorySize, smem);

    int nsm = 148;
    cudaDeviceGetAttribute(&nsm, cudaDevAttrMultiProcessorCount, 0);

    router_kernel<<<nsm, 256, smem>>>(h, Ww, bw, Wn, bn, eps, (float*)d_out);
}